// round 3
// baseline (speedup 1.0000x reference)
#include <cuda_runtime.h>
#include <stdint.h>

#define B_  2
#define M_  2048
#define N_  2048
#define D_  1024
#define NH_ 16
#define DH_ 64

// Scratch (device globals: no allocation allowed)
__device__ float g_Q[(size_t)B_ * M_ * D_];
__device__ float g_K[(size_t)B_ * N_ * D_];
__device__ float g_V[(size_t)B_ * N_ * D_];
__device__ float g_C[(size_t)B_ * M_ * D_];
__device__ unsigned char g_mask[B_ * N_];

// ---------------------------------------------------------------------------
// helpers
// ---------------------------------------------------------------------------
__device__ __forceinline__ unsigned f2tf(float x) {
    unsigned u; asm("cvt.rna.tf32.f32 %0, %1;" : "=r"(u) : "f"(x)); return u;
}
__device__ __forceinline__ float ex2(float x) {
    float y; asm("ex2.approx.f32 %0, %1;" : "=f"(y) : "f"(x)); return y;
}
__device__ __forceinline__ void mma8(float* c, unsigned a0, unsigned a1, unsigned a2, unsigned a3,
                                     unsigned b0, unsigned b1) {
    asm volatile(
        "mma.sync.aligned.m16n8k8.row.col.f32.tf32.tf32.f32 "
        "{%0,%1,%2,%3},{%4,%5,%6,%7},{%8,%9},{%0,%1,%2,%3};\n"
        : "+f"(c[0]), "+f"(c[1]), "+f"(c[2]), "+f"(c[3])
        : "r"(a0), "r"(a1), "r"(a2), "r"(a3), "r"(b0), "r"(b1));
}
__device__ __forceinline__ void cpasync16(void* dst, const void* src) {
    unsigned d = (unsigned)__cvta_generic_to_shared(dst);
    asm volatile("cp.async.cg.shared.global [%0], [%1], 16;\n" :: "r"(d), "l"(src));
}
#define CP_COMMIT() asm volatile("cp.async.commit_group;\n" ::: "memory")
#define CP_WAIT1()  asm volatile("cp.async.wait_group 1;\n" ::: "memory")

// ---------------------------------------------------------------------------
// Mask dtype sniffer + expander (bool may arrive as u8 / i32 / f32)
// ---------------------------------------------------------------------------
__global__ void mask_expand_kernel(const unsigned char* __restrict__ raw) {
    __shared__ int s_not_int, s_not_float;
    if (threadIdx.x == 0) { s_not_int = 0; s_not_float = 0; }
    __syncthreads();
    const unsigned int* w = (const unsigned int*)raw;
    for (int i = threadIdx.x; i < 1024; i += blockDim.x) {
        unsigned int x = w[i];
        if (x != 0u && x != 1u)          atomicOr(&s_not_int, 1);
        if (x != 0u && x != 0x3F800000u) atomicOr(&s_not_float, 1);
    }
    __syncthreads();
    int mode = (!s_not_int) ? 0 : ((!s_not_float) ? 1 : 2);
    if (mode == 2) {
        for (int i = threadIdx.x; i < B_ * N_; i += blockDim.x)
            g_mask[i] = raw[i] ? 1 : 0;
    } else {
        for (int i = threadIdx.x; i < B_ * N_; i += blockDim.x)
            g_mask[i] = w[i] ? 1 : 0;
    }
}

// ---------------------------------------------------------------------------
// TF32 GEMM body: C[., 1024] = A[., 1024] @ B[1024, 1024], row-major fp32.
// 128x128 block, BK=32, cp.async 2-stage double buffer, 256 threads.
// ---------------------------------------------------------------------------
#define GA_STR 36
#define GB_STR 136
#define GA_WORDS (128 * GA_STR)               // 4608
#define GB_WORDS (32 * GB_STR)                // 4352
#define GEMM_SMEM_BYTES ((GA_WORDS + GB_WORDS) * 2 * 4)  // 71680

__device__ __forceinline__ void gemm_stage_load(
    const float* __restrict__ A, const float* __restrict__ Bm,
    int rowBase, int colBase, int k0, float* As, float* Bs, int tid)
{
#pragma unroll
    for (int i = 0; i < 4; ++i) {
        int f = tid + i * 256;
        int r = f >> 3, c = (f & 7) * 4;
        cpasync16(As + r * GA_STR + c, A + (size_t)(rowBase + r) * D_ + k0 + c);
    }
#pragma unroll
    for (int i = 0; i < 4; ++i) {
        int f = tid + i * 256;
        int r = f >> 5, c = (f & 31) * 4;
        cpasync16(Bs + r * GB_STR + c, Bm + (size_t)(k0 + r) * D_ + colBase + c);
    }
}

__device__ __forceinline__ void gemm_body(
    const float* __restrict__ A, const float* __restrict__ Bm, float* __restrict__ C)
{
    extern __shared__ float gs[];
    float* Abuf[2] = { gs, gs + GA_WORDS };
    float* Bbuf[2] = { gs + 2 * GA_WORDS, gs + 2 * GA_WORDS + GB_WORDS };

    const int tid  = threadIdx.x;
    const int warp = tid >> 5, lane = tid & 31;
    const int g = lane >> 2, t = lane & 3;
    const int wm = (warp >> 2) * 64;
    const int wn = (warp & 3) * 32;
    const int rowBase = blockIdx.y * 128;
    const int colBase = blockIdx.x * 128;

    float acc[4][4][4];
#pragma unroll
    for (int i = 0; i < 4; ++i)
#pragma unroll
        for (int j = 0; j < 4; ++j)
#pragma unroll
            for (int k = 0; k < 4; ++k) acc[i][j][k] = 0.f;

    gemm_stage_load(A, Bm, rowBase, colBase, 0, Abuf[0], Bbuf[0], tid);
    CP_COMMIT();

    const int nsteps = D_ / 32;   // 32
    for (int it = 0; it < nsteps; ++it) {
        const int cur = it & 1;
        if (it + 1 < nsteps)
            gemm_stage_load(A, Bm, rowBase, colBase, (it + 1) * 32,
                            Abuf[cur ^ 1], Bbuf[cur ^ 1], tid);
        CP_COMMIT();
        CP_WAIT1();
        __syncthreads();

        const float* As = Abuf[cur];
        const float* Bs = Bbuf[cur];
#pragma unroll
        for (int kk = 0; kk < 4; ++kk) {
            const int kb = kk * 8;
            unsigned a[4][4], bf[4][2];
#pragma unroll
            for (int mt = 0; mt < 4; ++mt) {
                int mr = wm + mt * 16;
                a[mt][0] = f2tf(As[(mr + g) * GA_STR + kb + t]);
                a[mt][1] = f2tf(As[(mr + g + 8) * GA_STR + kb + t]);
                a[mt][2] = f2tf(As[(mr + g) * GA_STR + kb + t + 4]);
                a[mt][3] = f2tf(As[(mr + g + 8) * GA_STR + kb + t + 4]);
            }
#pragma unroll
            for (int nt = 0; nt < 4; ++nt) {
                int nc = wn + nt * 8 + g;
                bf[nt][0] = f2tf(Bs[(kb + t) * GB_STR + nc]);
                bf[nt][1] = f2tf(Bs[(kb + t + 4) * GB_STR + nc]);
            }
#pragma unroll
            for (int mt = 0; mt < 4; ++mt)
#pragma unroll
                for (int nt = 0; nt < 4; ++nt)
                    mma8(acc[mt][nt], a[mt][0], a[mt][1], a[mt][2], a[mt][3],
                         bf[nt][0], bf[nt][1]);
        }
        __syncthreads();
    }

#pragma unroll
    for (int mt = 0; mt < 4; ++mt) {
        int r0 = rowBase + wm + mt * 16 + g;
#pragma unroll
        for (int nt = 0; nt < 4; ++nt) {
            int c0 = colBase + wn + nt * 8 + 2 * t;
            *(float2*)(C + (size_t)r0 * D_ + c0) =
                make_float2(acc[mt][nt][0], acc[mt][nt][1]);
            *(float2*)(C + (size_t)(r0 + 8) * D_ + c0) =
                make_float2(acc[mt][nt][2], acc[mt][nt][3]);
        }
    }
}

__global__ __launch_bounds__(256) void gemm_qkv(
    const float* __restrict__ q, const float* __restrict__ kv,
    const float* __restrict__ WQ, const float* __restrict__ WK,
    const float* __restrict__ WV)
{
    const float *A, *Bm; float* C;
    if (blockIdx.z == 0)      { A = q;  Bm = WQ; C = g_Q; }
    else if (blockIdx.z == 1) { A = kv; Bm = WK; C = g_K; }
    else                      { A = kv; Bm = WV; C = g_V; }
    gemm_body(A, Bm, C);
}

__global__ __launch_bounds__(256) void gemm_single(
    const float* __restrict__ A, const float* __restrict__ Bm, float* __restrict__ C)
{
    gemm_body(A, Bm, C);
}

// ---------------------------------------------------------------------------
// TF32 flash attention. Block = 128 query rows of one (b,h). 4 warps, each
// warp owns 32 rows (two m16 tiles). K-tile = 64 keys. Grid: (M/128, NH, B).
// ---------------------------------------------------------------------------
#define QS_STR 68
#define KS_STR 68
#define VS_STR 72
#define PS_STR 68
#define AQS_OFF 0
#define AKS_OFF (128 * QS_STR)                // 8704
#define AVS_OFF (AKS_OFF + 64 * KS_STR)       // 13056
#define APS_OFF (AVS_OFF + 64 * VS_STR)       // 17664
#define AMB_OFF (APS_OFF + 128 * PS_STR)      // 26368
#define ATT_SMEM_BYTES ((AMB_OFF + 64) * 4)   // 105728

#define M_INIT (-1.0e4f)
#define MASK_BIAS (-1.0e9f)

__global__ __launch_bounds__(128) void attn_tc(
    const float* __restrict__ Q, const float* __restrict__ K,
    const float* __restrict__ V, float* __restrict__ Cout)
{
    extern __shared__ unsigned smemu[];
    unsigned* Qs = smemu + AQS_OFF;
    unsigned* Ks = smemu + AKS_OFF;
    unsigned* Vs = smemu + AVS_OFF;
    unsigned* Ps = smemu + APS_OFF;
    float* mbias = (float*)(smemu + AMB_OFF);

    const int mtile = blockIdx.x, h = blockIdx.y, b = blockIdx.z;
    const int tid = threadIdx.x;
    const int warp = tid >> 5, lane = tid & 31;
    const int g = lane >> 2, t = lane & 3;
    const int mb0 = warp * 32;

    // Load Q tile: thread tid -> row tid (128 rows x 64), scale+log2e folded
    {
        const float SC = 0.125f * 1.44269504f;
        const float4* qrow = (const float4*)(Q + ((size_t)(b * M_ + mtile * 128 + tid)) * D_ + h * DH_);
#pragma unroll
        for (int i = 0; i < 16; ++i) {
            float4 v = qrow[i];
            Qs[tid * QS_STR + 4 * i + 0] = f2tf(v.x * SC);
            Qs[tid * QS_STR + 4 * i + 1] = f2tf(v.y * SC);
            Qs[tid * QS_STR + 4 * i + 2] = f2tf(v.z * SC);
            Qs[tid * QS_STR + 4 * i + 3] = f2tf(v.w * SC);
        }
    }

    float mS[2][2], lS[2][2];
#pragma unroll
    for (int i = 0; i < 2; ++i) { mS[i][0] = M_INIT; mS[i][1] = M_INIT; lS[i][0] = 0.f; lS[i][1] = 0.f; }
    float o[2][8][4];
#pragma unroll
    for (int mt = 0; mt < 2; ++mt)
#pragma unroll
        for (int i = 0; i < 8; ++i)
#pragma unroll
            for (int j = 0; j < 4; ++j) o[mt][i][j] = 0.f;

    for (int kt = 0; kt < N_ / 64; ++kt) {
        __syncthreads();   // previous Ks/Vs fully consumed
        {
            const int r = tid >> 1, ch = (tid & 1) * 32;
            const float4* krow = (const float4*)(K + ((size_t)(b * N_ + kt * 64 + r)) * D_ + h * DH_ + ch);
            const float4* vrow = (const float4*)(V + ((size_t)(b * N_ + kt * 64 + r)) * D_ + h * DH_ + ch);
#pragma unroll
            for (int i = 0; i < 8; ++i) {
                float4 kv = krow[i];
                Ks[r * KS_STR + ch + 4 * i + 0] = f2tf(kv.x);
                Ks[r * KS_STR + ch + 4 * i + 1] = f2tf(kv.y);
                Ks[r * KS_STR + ch + 4 * i + 2] = f2tf(kv.z);
                Ks[r * KS_STR + ch + 4 * i + 3] = f2tf(kv.w);
            }
#pragma unroll
            for (int i = 0; i < 8; ++i) {
                float4 vv = vrow[i];
                Vs[r * VS_STR + ch + 4 * i + 0] = f2tf(vv.x);
                Vs[r * VS_STR + ch + 4 * i + 1] = f2tf(vv.y);
                Vs[r * VS_STR + ch + 4 * i + 2] = f2tf(vv.z);
                Vs[r * VS_STR + ch + 4 * i + 3] = f2tf(vv.w);
            }
            if (tid < 64)
                mbias[tid] = g_mask[b * N_ + kt * 64 + tid] ? MASK_BIAS : 0.f;
        }
        __syncthreads();

        // Per m-tile: S = Q K^T, softmax, write P (keeps register pressure low)
#pragma unroll
        for (int mt = 0; mt < 2; ++mt) {
            const int mr = mb0 + mt * 16;
            float s[8][4];
#pragma unroll
            for (int i = 0; i < 8; ++i)
#pragma unroll
                for (int j = 0; j < 4; ++j) s[i][j] = 0.f;

#pragma unroll
            for (int kk = 0; kk < 8; ++kk) {
                const int kb = kk * 8;
                unsigned a0 = Qs[(mr + g) * QS_STR + kb + t];
                unsigned a1 = Qs[(mr + g + 8) * QS_STR + kb + t];
                unsigned a2 = Qs[(mr + g) * QS_STR + kb + t + 4];
                unsigned a3 = Qs[(mr + g + 8) * QS_STR + kb + t + 4];
#pragma unroll
                for (int nt = 0; nt < 8; ++nt) {
                    unsigned b0 = Ks[(nt * 8 + g) * KS_STR + kb + t];
                    unsigned b1 = Ks[(nt * 8 + g) * KS_STR + kb + t + 4];
                    mma8(s[nt], a0, a1, a2, a3, b0, b1);
                }
            }

            float mx0 = -3.0e38f, mx1 = -3.0e38f;
#pragma unroll
            for (int nt = 0; nt < 8; ++nt) {
                float b0v = mbias[nt * 8 + 2 * t];
                float b1v = mbias[nt * 8 + 2 * t + 1];
                s[nt][0] += b0v; s[nt][1] += b1v;
                s[nt][2] += b0v; s[nt][3] += b1v;
                mx0 = fmaxf(mx0, fmaxf(s[nt][0], s[nt][1]));
                mx1 = fmaxf(mx1, fmaxf(s[nt][2], s[nt][3]));
            }
            mx0 = fmaxf(mx0, __shfl_xor_sync(0xFFFFFFFFu, mx0, 1));
            mx0 = fmaxf(mx0, __shfl_xor_sync(0xFFFFFFFFu, mx0, 2));
            mx1 = fmaxf(mx1, __shfl_xor_sync(0xFFFFFFFFu, mx1, 1));
            mx1 = fmaxf(mx1, __shfl_xor_sync(0xFFFFFFFFu, mx1, 2));
            float nm0 = fmaxf(mS[mt][0], mx0), nm1 = fmaxf(mS[mt][1], mx1);
            float cr0 = ex2(mS[mt][0] - nm0), cr1 = ex2(mS[mt][1] - nm1);
            mS[mt][0] = nm0; mS[mt][1] = nm1;

            float rs0 = 0.f, rs1 = 0.f;
#pragma unroll
            for (int nt = 0; nt < 8; ++nt) {
                s[nt][0] = ex2(s[nt][0] - nm0);
                s[nt][1] = ex2(s[nt][1] - nm0);
                s[nt][2] = ex2(s[nt][2] - nm1);
                s[nt][3] = ex2(s[nt][3] - nm1);
                rs0 += s[nt][0] + s[nt][1];
                rs1 += s[nt][2] + s[nt][3];
                o[mt][nt][0] *= cr0; o[mt][nt][1] *= cr0;
                o[mt][nt][2] *= cr1; o[mt][nt][3] *= cr1;
                Ps[(mr + g) * PS_STR + nt * 8 + 2 * t]         = f2tf(s[nt][0]);
                Ps[(mr + g) * PS_STR + nt * 8 + 2 * t + 1]     = f2tf(s[nt][1]);
                Ps[(mr + g + 8) * PS_STR + nt * 8 + 2 * t]     = f2tf(s[nt][2]);
                Ps[(mr + g + 8) * PS_STR + nt * 8 + 2 * t + 1] = f2tf(s[nt][3]);
            }
            lS[mt][0] = lS[mt][0] * cr0 + rs0;
            lS[mt][1] = lS[mt][1] * cr1 + rs1;
        }
        __syncwarp();

        // O += P V for BOTH m-tiles (V b-fragments shared)
#pragma unroll
        for (int kk = 0; kk < 8; ++kk) {
            const int kb = kk * 8;
            unsigned a[2][4];
#pragma unroll
            for (int mt = 0; mt < 2; ++mt) {
                const int mr = mb0 + mt * 16;
                a[mt][0] = Ps[(mr + g) * PS_STR + kb + t];
                a[mt][1] = Ps[(mr + g + 8) * PS_STR + kb + t];
                a[mt][2] = Ps[(mr + g) * PS_STR + kb + t + 4];
                a[mt][3] = Ps[(mr + g + 8) * PS_STR + kb + t + 4];
            }
#pragma unroll
            for (int nt = 0; nt < 8; ++nt) {
                unsigned b0 = Vs[(kb + t) * VS_STR + nt * 8 + g];
                unsigned b1 = Vs[(kb + t + 4) * VS_STR + nt * 8 + g];
                mma8(o[0][nt], a[0][0], a[0][1], a[0][2], a[0][3], b0, b1);
                mma8(o[1][nt], a[1][0], a[1][1], a[1][2], a[1][3], b0, b1);
            }
        }
        __syncwarp();   // Ps reads done before next tile rewrites
    }

    // finalize both m-tiles
#pragma unroll
    for (int mt = 0; mt < 2; ++mt) {
        float l0 = lS[mt][0], l1 = lS[mt][1];
        l0 += __shfl_xor_sync(0xFFFFFFFFu, l0, 1);
        l0 += __shfl_xor_sync(0xFFFFFFFFu, l0, 2);
        l1 += __shfl_xor_sync(0xFFFFFFFFu, l1, 1);
        l1 += __shfl_xor_sync(0xFFFFFFFFu, l1, 2);
        float inv0 = 1.f / l0, inv1 = 1.f / l1;

        const int gr0 = mtile * 128 + mb0 + mt * 16 + g;
        const int gr1 = gr0 + 8;
#pragma unroll
        for (int nt = 0; nt < 8; ++nt) {
            int col = h * DH_ + nt * 8 + 2 * t;
            *(float2*)(Cout + ((size_t)(b * M_ + gr0)) * D_ + col) =
                make_float2(o[mt][nt][0] * inv0, o[mt][nt][1] * inv0);
            *(float2*)(Cout + ((size_t)(b * M_ + gr1)) * D_ + col) =
                make_float2(o[mt][nt][2] * inv1, o[mt][nt][3] * inv1);
        }
    }
}

// ---------------------------------------------------------------------------
// Launch. Inputs: query, key_value, key_padding_mask, W_Q, W_K, W_V, W_O
// ---------------------------------------------------------------------------
extern "C" void kernel_launch(void* const* d_in, const int* in_sizes, int n_in,
                              void* d_out, int out_size)
{
    const float* query = (const float*)d_in[0];
    const float* keyv  = (const float*)d_in[1];
    const unsigned char* mask_raw = (const unsigned char*)d_in[2];
    const float* W_Q = (const float*)d_in[3];
    const float* W_K = (const float*)d_in[4];
    const float* W_V = (const float*)d_in[5];
    const float* W_O = (const float*)d_in[6];
    float* out = (float*)d_out;

    float *gQ, *gK, *gV, *gC;
    cudaGetSymbolAddress((void**)&gQ, g_Q);
    cudaGetSymbolAddress((void**)&gK, g_K);
    cudaGetSymbolAddress((void**)&gV, g_V);
    cudaGetSymbolAddress((void**)&gC, g_C);

    cudaFuncSetAttribute(gemm_qkv,    cudaFuncAttributeMaxDynamicSharedMemorySize, GEMM_SMEM_BYTES);
    cudaFuncSetAttribute(gemm_single, cudaFuncAttributeMaxDynamicSharedMemorySize, GEMM_SMEM_BYTES);
    cudaFuncSetAttribute(attn_tc,     cudaFuncAttributeMaxDynamicSharedMemorySize, ATT_SMEM_BYTES);

    mask_expand_kernel<<<1, 1024>>>(mask_raw);

    dim3 gqkv(D_ / 128, (B_ * M_) / 128, 3);
    gemm_qkv<<<gqkv, 256, GEMM_SMEM_BYTES>>>(query, keyv, W_Q, W_K, W_V);

    dim3 gattn(M_ / 128, NH_, B_);
    attn_tc<<<gattn, 128, ATT_SMEM_BYTES>>>(gQ, gK, gV, gC);

    dim3 gout(D_ / 128, (B_ * M_) / 128);
    gemm_single<<<gout, 256, GEMM_SMEM_BYTES>>>(gC, W_O, out);
}

// round 4
// speedup vs baseline: 1.6684x; 1.6684x over previous
#include <cuda_runtime.h>
#include <stdint.h>

#define B_  2
#define M_  2048
#define N_  2048
#define D_  1024
#define NH_ 16
#define DH_ 64

// Scratch (device globals: no allocation allowed)
__device__ float g_Q[(size_t)B_ * M_ * D_];
__device__ float g_K[(size_t)B_ * N_ * D_];
__device__ float g_V[(size_t)B_ * N_ * D_];
__device__ float g_C[(size_t)B_ * M_ * D_];
__device__ unsigned char g_mask[B_ * N_];

// ---------------------------------------------------------------------------
// helpers
// ---------------------------------------------------------------------------
__device__ __forceinline__ unsigned f2tf(float x) {
    unsigned u; asm("cvt.rna.tf32.f32 %0, %1;" : "=r"(u) : "f"(x)); return u;
}
__device__ __forceinline__ float ex2(float x) {
    float y; asm("ex2.approx.f32 %0, %1;" : "=f"(y) : "f"(x)); return y;
}
__device__ __forceinline__ void mma8(float* c, unsigned a0, unsigned a1, unsigned a2, unsigned a3,
                                     unsigned b0, unsigned b1) {
    asm volatile(
        "mma.sync.aligned.m16n8k8.row.col.f32.tf32.tf32.f32 "
        "{%0,%1,%2,%3},{%4,%5,%6,%7},{%8,%9},{%0,%1,%2,%3};\n"
        : "+f"(c[0]), "+f"(c[1]), "+f"(c[2]), "+f"(c[3])
        : "r"(a0), "r"(a1), "r"(a2), "r"(a3), "r"(b0), "r"(b1));
}
__device__ __forceinline__ void cpasync16(void* dst, const void* src) {
    unsigned d = (unsigned)__cvta_generic_to_shared(dst);
    asm volatile("cp.async.cg.shared.global [%0], [%1], 16;\n" :: "r"(d), "l"(src));
}
#define CP_COMMIT() asm volatile("cp.async.commit_group;\n" ::: "memory")
#define CP_WAIT1()  asm volatile("cp.async.wait_group 1;\n" ::: "memory")
#define CP_WAIT0()  asm volatile("cp.async.wait_group 0;\n" ::: "memory")

// ---------------------------------------------------------------------------
// Mask dtype sniffer + expander (bool may arrive as u8 / i32 / f32)
// ---------------------------------------------------------------------------
__global__ void mask_expand_kernel(const unsigned char* __restrict__ raw) {
    __shared__ int s_not_int, s_not_float;
    if (threadIdx.x == 0) { s_not_int = 0; s_not_float = 0; }
    __syncthreads();
    const unsigned int* w = (const unsigned int*)raw;
    for (int i = threadIdx.x; i < 1024; i += blockDim.x) {
        unsigned int x = w[i];
        if (x != 0u && x != 1u)          atomicOr(&s_not_int, 1);
        if (x != 0u && x != 0x3F800000u) atomicOr(&s_not_float, 1);
    }
    __syncthreads();
    int mode = (!s_not_int) ? 0 : ((!s_not_float) ? 1 : 2);
    if (mode == 2) {
        for (int i = threadIdx.x; i < B_ * N_; i += blockDim.x)
            g_mask[i] = raw[i] ? 1 : 0;
    } else {
        for (int i = threadIdx.x; i < B_ * N_; i += blockDim.x)
            g_mask[i] = w[i] ? 1 : 0;
    }
}

// ---------------------------------------------------------------------------
// TF32 GEMM: C[.,1024] = A[.,1024] @ B[1024,1024] row-major fp32.
// 128x128 block tile, BK=16, cp.async 2-stage double buffer (raw fp32 in
// smem, tf32 convert at fragment load), 256 threads, <=127 regs (2 blk/SM).
// ---------------------------------------------------------------------------
#define GA_STR 20                       // 16 + 4 pad (words)
#define GB_STR 136                      // 128 + 8 pad
#define GA_WORDS (128 * GA_STR)         // 2560
#define GB_WORDS (16 * GB_STR)          // 2176

__device__ __forceinline__ void gemm_stage_load(
    const float* __restrict__ A, const float* __restrict__ Bm,
    int rowBase, int colBase, int k0, float* As, float* Bs, int tid)
{
#pragma unroll
    for (int i = 0; i < 2; ++i) {
        int f = tid + i * 256;
        int r = f >> 2, c = (f & 3) * 4;           // 128 rows x 16 cols
        cpasync16(As + r * GA_STR + c, A + (size_t)(rowBase + r) * D_ + k0 + c);
    }
#pragma unroll
    for (int i = 0; i < 2; ++i) {
        int f = tid + i * 256;
        int r = f >> 5, c = (f & 31) * 4;          // 16 rows x 128 cols
        cpasync16(Bs + r * GB_STR + c, Bm + (size_t)(k0 + r) * D_ + colBase + c);
    }
}

__device__ __forceinline__ void gemm_body(
    const float* __restrict__ A, const float* __restrict__ Bm, float* __restrict__ C)
{
    __shared__ float As[2][GA_WORDS];
    __shared__ float Bs[2][GB_WORDS];

    const int tid  = threadIdx.x;
    const int warp = tid >> 5, lane = tid & 31;
    const int g = lane >> 2, t = lane & 3;
    const int wm = (warp >> 2) * 64;
    const int wn = (warp & 3) * 32;
    const int rowBase = blockIdx.y * 128;
    const int colBase = blockIdx.x * 128;

    float acc[4][4][4];
#pragma unroll
    for (int i = 0; i < 4; ++i)
#pragma unroll
        for (int j = 0; j < 4; ++j)
#pragma unroll
            for (int k = 0; k < 4; ++k) acc[i][j][k] = 0.f;

    gemm_stage_load(A, Bm, rowBase, colBase, 0, As[0], Bs[0], tid);
    CP_COMMIT();

    const int NIT = D_ / 16;   // 64
    for (int it = 0; it < NIT; ++it) {
        const int cur = it & 1;
        if (it + 1 < NIT) {
            gemm_stage_load(A, Bm, rowBase, colBase, (it + 1) * 16,
                            As[cur ^ 1], Bs[cur ^ 1], tid);
            CP_COMMIT();
            CP_WAIT1();
        } else {
            CP_WAIT0();
        }
        __syncthreads();

        const float* Ac = As[cur];
        const float* Bc = Bs[cur];
#pragma unroll
        for (int kk = 0; kk < 2; ++kk) {
            const int kb = kk * 8;
            unsigned a[4][4], bf[4][2];
#pragma unroll
            for (int mt = 0; mt < 4; ++mt) {
                int mr = wm + mt * 16;
                a[mt][0] = f2tf(Ac[(mr + g) * GA_STR + kb + t]);
                a[mt][1] = f2tf(Ac[(mr + g + 8) * GA_STR + kb + t]);
                a[mt][2] = f2tf(Ac[(mr + g) * GA_STR + kb + t + 4]);
                a[mt][3] = f2tf(Ac[(mr + g + 8) * GA_STR + kb + t + 4]);
            }
#pragma unroll
            for (int nt = 0; nt < 4; ++nt) {
                int nc = wn + nt * 8 + g;
                bf[nt][0] = f2tf(Bc[(kb + t) * GB_STR + nc]);
                bf[nt][1] = f2tf(Bc[(kb + t + 4) * GB_STR + nc]);
            }
#pragma unroll
            for (int mt = 0; mt < 4; ++mt)
#pragma unroll
                for (int nt = 0; nt < 4; ++nt)
                    mma8(acc[mt][nt], a[mt][0], a[mt][1], a[mt][2], a[mt][3],
                         bf[nt][0], bf[nt][1]);
        }
        __syncthreads();
    }

#pragma unroll
    for (int mt = 0; mt < 4; ++mt) {
        int r0 = rowBase + wm + mt * 16 + g;
#pragma unroll
        for (int nt = 0; nt < 4; ++nt) {
            int c0 = colBase + wn + nt * 8 + 2 * t;
            *(float2*)(C + (size_t)r0 * D_ + c0) =
                make_float2(acc[mt][nt][0], acc[mt][nt][1]);
            *(float2*)(C + (size_t)(r0 + 8) * D_ + c0) =
                make_float2(acc[mt][nt][2], acc[mt][nt][3]);
        }
    }
}

__global__ __launch_bounds__(256, 2) void gemm_qkv(
    const float* __restrict__ q, const float* __restrict__ kv,
    const float* __restrict__ WQ, const float* __restrict__ WK,
    const float* __restrict__ WV)
{
    const float *A, *Bm; float* C;
    if (blockIdx.z == 0)      { A = q;  Bm = WQ; C = g_Q; }
    else if (blockIdx.z == 1) { A = kv; Bm = WK; C = g_K; }
    else                      { A = kv; Bm = WV; C = g_V; }
    gemm_body(A, Bm, C);
}

__global__ __launch_bounds__(256, 2) void gemm_single(
    const float* __restrict__ A, const float* __restrict__ Bm, float* __restrict__ C)
{
    gemm_body(A, Bm, C);
}

// ---------------------------------------------------------------------------
// TF32 flash attention (R2-proven). Block = 64 query rows of one (b,h).
// 4 warps x 16 rows. Grid: (M/64, NH, B). Dynamic smem.
// ---------------------------------------------------------------------------
#define QS_STR 68
#define KS_STR 68
#define VS_STR 72
#define PS_STR 68
#define QS_OFF 0
#define KS_OFF (64 * QS_STR)
#define VS_OFF (KS_OFF + 64 * KS_STR)
#define PS_OFF (VS_OFF + 64 * VS_STR)
#define MB_OFF (PS_OFF + 64 * PS_STR)
#define SMEM_WORDS (MB_OFF + 64)

#define M_INIT (-1.0e4f)
#define MASK_BIAS (-1.0e9f)

__global__ __launch_bounds__(128) void attn_tc(
    const float* __restrict__ Q, const float* __restrict__ K,
    const float* __restrict__ V, float* __restrict__ Cout)
{
    extern __shared__ unsigned smemu[];
    unsigned* Qs = smemu + QS_OFF;
    unsigned* Ks = smemu + KS_OFF;
    unsigned* Vs = smemu + VS_OFF;
    unsigned* Ps = smemu + PS_OFF;
    float* mbias = (float*)(smemu + MB_OFF);

    const int mtile = blockIdx.x, h = blockIdx.y, b = blockIdx.z;
    const int tid = threadIdx.x;
    const int warp = tid >> 5, lane = tid & 31;
    const int g = lane >> 2, t = lane & 3;
    const int mb = warp * 16;

    {
        const int r = tid >> 1, ch = (tid & 1) * 32;
        const float SC = 0.125f * 1.44269504f;
        const float4* qrow = (const float4*)(Q + ((size_t)(b * M_ + mtile * 64 + r)) * D_ + h * DH_ + ch);
#pragma unroll
        for (int i = 0; i < 8; ++i) {
            float4 v = qrow[i];
            Qs[r * QS_STR + ch + 4 * i + 0] = f2tf(v.x * SC);
            Qs[r * QS_STR + ch + 4 * i + 1] = f2tf(v.y * SC);
            Qs[r * QS_STR + ch + 4 * i + 2] = f2tf(v.z * SC);
            Qs[r * QS_STR + ch + 4 * i + 3] = f2tf(v.w * SC);
        }
    }

    float m0 = M_INIT, m1 = M_INIT, l0 = 0.f, l1 = 0.f;
    float o[8][4];
#pragma unroll
    for (int i = 0; i < 8; ++i)
#pragma unroll
        for (int j = 0; j < 4; ++j) o[i][j] = 0.f;

    for (int kt = 0; kt < N_ / 64; ++kt) {
        __syncthreads();
        {
            const int r = tid >> 1, ch = (tid & 1) * 32;
            const float4* krow = (const float4*)(K + ((size_t)(b * N_ + kt * 64 + r)) * D_ + h * DH_ + ch);
            const float4* vrow = (const float4*)(V + ((size_t)(b * N_ + kt * 64 + r)) * D_ + h * DH_ + ch);
#pragma unroll
            for (int i = 0; i < 8; ++i) {
                float4 kv = krow[i];
                Ks[r * KS_STR + ch + 4 * i + 0] = f2tf(kv.x);
                Ks[r * KS_STR + ch + 4 * i + 1] = f2tf(kv.y);
                Ks[r * KS_STR + ch + 4 * i + 2] = f2tf(kv.z);
                Ks[r * KS_STR + ch + 4 * i + 3] = f2tf(kv.w);
            }
#pragma unroll
            for (int i = 0; i < 8; ++i) {
                float4 vv = vrow[i];
                Vs[r * VS_STR + ch + 4 * i + 0] = f2tf(vv.x);
                Vs[r * VS_STR + ch + 4 * i + 1] = f2tf(vv.y);
                Vs[r * VS_STR + ch + 4 * i + 2] = f2tf(vv.z);
                Vs[r * VS_STR + ch + 4 * i + 3] = f2tf(vv.w);
            }
            if (tid < 64)
                mbias[tid] = g_mask[b * N_ + kt * 64 + tid] ? MASK_BIAS : 0.f;
        }
        __syncthreads();

        float s[8][4];
#pragma unroll
        for (int i = 0; i < 8; ++i)
#pragma unroll
            for (int j = 0; j < 4; ++j) s[i][j] = 0.f;

#pragma unroll
        for (int kk = 0; kk < 8; ++kk) {
            const int kb = kk * 8;
            unsigned a0 = Qs[(mb + g) * QS_STR + kb + t];
            unsigned a1 = Qs[(mb + g + 8) * QS_STR + kb + t];
            unsigned a2 = Qs[(mb + g) * QS_STR + kb + t + 4];
            unsigned a3 = Qs[(mb + g + 8) * QS_STR + kb + t + 4];
#pragma unroll
            for (int nt = 0; nt < 8; ++nt) {
                unsigned b0 = Ks[(nt * 8 + g) * KS_STR + kb + t];
                unsigned b1 = Ks[(nt * 8 + g) * KS_STR + kb + t + 4];
                mma8(s[nt], a0, a1, a2, a3, b0, b1);
            }
        }

        float mx0 = -3.0e38f, mx1 = -3.0e38f;
#pragma unroll
        for (int nt = 0; nt < 8; ++nt) {
            float b0 = mbias[nt * 8 + 2 * t];
            float b1 = mbias[nt * 8 + 2 * t + 1];
            s[nt][0] += b0; s[nt][1] += b1;
            s[nt][2] += b0; s[nt][3] += b1;
            mx0 = fmaxf(mx0, fmaxf(s[nt][0], s[nt][1]));
            mx1 = fmaxf(mx1, fmaxf(s[nt][2], s[nt][3]));
        }
        mx0 = fmaxf(mx0, __shfl_xor_sync(0xFFFFFFFFu, mx0, 1));
        mx0 = fmaxf(mx0, __shfl_xor_sync(0xFFFFFFFFu, mx0, 2));
        mx1 = fmaxf(mx1, __shfl_xor_sync(0xFFFFFFFFu, mx1, 1));
        mx1 = fmaxf(mx1, __shfl_xor_sync(0xFFFFFFFFu, mx1, 2));
        float nm0 = fmaxf(m0, mx0), nm1 = fmaxf(m1, mx1);
        float cr0 = ex2(m0 - nm0), cr1 = ex2(m1 - nm1);
        m0 = nm0; m1 = nm1;

        float rs0 = 0.f, rs1 = 0.f;
#pragma unroll
        for (int nt = 0; nt < 8; ++nt) {
            s[nt][0] = ex2(s[nt][0] - nm0);
            s[nt][1] = ex2(s[nt][1] - nm0);
            s[nt][2] = ex2(s[nt][2] - nm1);
            s[nt][3] = ex2(s[nt][3] - nm1);
            rs0 += s[nt][0] + s[nt][1];
            rs1 += s[nt][2] + s[nt][3];
        }
        l0 = l0 * cr0 + rs0;
        l1 = l1 * cr1 + rs1;

#pragma unroll
        for (int nt = 0; nt < 8; ++nt) {
            o[nt][0] *= cr0; o[nt][1] *= cr0;
            o[nt][2] *= cr1; o[nt][3] *= cr1;
            Ps[(mb + g) * PS_STR + nt * 8 + 2 * t]         = f2tf(s[nt][0]);
            Ps[(mb + g) * PS_STR + nt * 8 + 2 * t + 1]     = f2tf(s[nt][1]);
            Ps[(mb + g + 8) * PS_STR + nt * 8 + 2 * t]     = f2tf(s[nt][2]);
            Ps[(mb + g + 8) * PS_STR + nt * 8 + 2 * t + 1] = f2tf(s[nt][3]);
        }
        __syncwarp();

#pragma unroll
        for (int kk = 0; kk < 8; ++kk) {
            const int kb = kk * 8;
            unsigned a0 = Ps[(mb + g) * PS_STR + kb + t];
            unsigned a1 = Ps[(mb + g + 8) * PS_STR + kb + t];
            unsigned a2 = Ps[(mb + g) * PS_STR + kb + t + 4];
            unsigned a3 = Ps[(mb + g + 8) * PS_STR + kb + t + 4];
#pragma unroll
            for (int nt = 0; nt < 8; ++nt) {
                unsigned b0 = Vs[(kb + t) * VS_STR + nt * 8 + g];
                unsigned b1 = Vs[(kb + t + 4) * VS_STR + nt * 8 + g];
                mma8(o[nt], a0, a1, a2, a3, b0, b1);
            }
        }
        __syncwarp();
    }

    l0 += __shfl_xor_sync(0xFFFFFFFFu, l0, 1);
    l0 += __shfl_xor_sync(0xFFFFFFFFu, l0, 2);
    l1 += __shfl_xor_sync(0xFFFFFFFFu, l1, 1);
    l1 += __shfl_xor_sync(0xFFFFFFFFu, l1, 2);
    float inv0 = 1.f / l0, inv1 = 1.f / l1;

    const int gr0 = mtile * 64 + mb + g;
    const int gr1 = gr0 + 8;
#pragma unroll
    for (int nt = 0; nt < 8; ++nt) {
        int col = h * DH_ + nt * 8 + 2 * t;
        *(float2*)(Cout + ((size_t)(b * M_ + gr0)) * D_ + col) =
            make_float2(o[nt][0] * inv0, o[nt][1] * inv0);
        *(float2*)(Cout + ((size_t)(b * M_ + gr1)) * D_ + col) =
            make_float2(o[nt][2] * inv1, o[nt][3] * inv1);
    }
}

// ---------------------------------------------------------------------------
// Launch. Inputs: query, key_value, key_padding_mask, W_Q, W_K, W_V, W_O
// ---------------------------------------------------------------------------
extern "C" void kernel_launch(void* const* d_in, const int* in_sizes, int n_in,
                              void* d_out, int out_size)
{
    const float* query = (const float*)d_in[0];
    const float* keyv  = (const float*)d_in[1];
    const unsigned char* mask_raw = (const unsigned char*)d_in[2];
    const float* W_Q = (const float*)d_in[3];
    const float* W_K = (const float*)d_in[4];
    const float* W_V = (const float*)d_in[5];
    const float* W_O = (const float*)d_in[6];
    float* out = (float*)d_out;

    float *gQ, *gK, *gV, *gC;
    cudaGetSymbolAddress((void**)&gQ, g_Q);
    cudaGetSymbolAddress((void**)&gK, g_K);
    cudaGetSymbolAddress((void**)&gV, g_V);
    cudaGetSymbolAddress((void**)&gC, g_C);

    cudaFuncSetAttribute(attn_tc, cudaFuncAttributeMaxDynamicSharedMemorySize,
                         SMEM_WORDS * 4);

    mask_expand_kernel<<<1, 1024>>>(mask_raw);

    dim3 gqkv(D_ / 128, (B_ * M_) / 128, 3);
    gemm_qkv<<<gqkv, 256>>>(query, keyv, W_Q, W_K, W_V);

    dim3 gattn(M_ / 64, NH_, B_);
    attn_tc<<<gattn, 128, SMEM_WORDS * 4>>>(gQ, gK, gV, gC);

    dim3 gout(D_ / 128, (B_ * M_) / 128);
    gemm_single<<<gout, 256>>>(gC, W_O, out);
}